// round 5
// baseline (speedup 1.0000x reference)
#include <cuda_runtime.h>
#include <math.h>

// Cross-kernel scratch (no allocations allowed).
__device__ float g_S, g_Rinf;
__device__ int   g_cut;       // first row of the constant region (multiple of 4), <= steps

#define SMEM_ROWS 4096        // 48 KB row buffer; freeze expected at ~290 rows

// ---------------------------------------------------------------------------
// Kernel A: thread 0 runs the serial recurrence into SMEM until S is bitwise
// frozen (checked every 8 iters; S monotone non-increasing, so equality over
// a chunk implies every step was a no-op, and shrinking I keeps it frozen).
// Then ALL 256 threads write: (a) head rows smem->gmem coalesced, and
// (b) the geometric transition rows via closed form:
//     m = k - r ; p = 2^(m*c) ; I = Irec*p ; R = Rinf - A*p ; S = S_frozen
// Fallback (no freeze within SMEM_ROWS): thread 0 finishes serially to gmem.
// ---------------------------------------------------------------------------
__global__ void __launch_bounds__(256, 1)
sir_scan_kernel(const float* __restrict__ x,
                const float* __restrict__ bw,
                const float* __restrict__ gw,
                int steps,
                float* __restrict__ out)
{
    __shared__ __align__(16) float s_rows[SMEM_ROWS * 3];
    __shared__ int    s_nrows, s_r, s_rsplit, s_cut;
    __shared__ float  s_S, s_Irec, s_A, s_Rinf;
    __shared__ double s_c;

    const int tid = threadIdx.x;

    if (tid == 0) {
        float S = x[0], I = x[1], R = x[2];
        const float pop  = __fadd_rn(__fadd_rn(x[0], x[1]), x[2]);
        const float g    = gw[0];
        const float beff = (pop == 1.0f) ? bw[0] : __fdiv_rn(bw[0], pop);
        const float omg  = __fsub_rn(1.0f, g);

        s_rows[0] = S; s_rows[1] = I; s_rows[2] = R;

        int i = 1;
        // Head rows 1..3 so chunks start at i=4 (keeps buffered count % 4 == 0).
        for (int h = 0; h < 3 && i < steps; ++h, ++i) {
            float u  = __fmaf_rn(beff, S, omg);
            float v  = __fmul_rn(beff, I);
            float nI = __fmul_rn(I, u);
            float nS = __fmaf_rn(-v, S, S);
            float nR = __fmaf_rn(g, I, R);
            S = nS; I = nI; R = nR;
            s_rows[3*i] = S; s_rows[3*i+1] = I; s_rows[3*i+2] = R;
        }

        bool frozen = false;
        const int cap = (steps < SMEM_ROWS) ? steps : SMEM_ROWS;
        for (; i + 8 <= cap; i += 8) {
            const float S0 = S;
            #pragma unroll
            for (int k = 0; k < 8; ++k) {
                float u  = __fmaf_rn(beff, S, omg);
                float v  = __fmul_rn(beff, I);
                float nI = __fmul_rn(I, u);
                float nS = __fmaf_rn(-v, S, S);
                float nR = __fmaf_rn(g, I, R);
                S = nS; I = nI; R = nR;
                float* row = s_rows + 3 * (i + k);
                row[0] = S; row[1] = I; row[2] = R;
            }
            if (S == S0) {
                float u = __fmaf_rn(beff, S, omg);
                if (u < 1.0f && u > 0.0f) {   // contracting: frozen permanently
                    i += 8;                    // rows [0, i) buffered; state = row i-1
                    frozen = true;
                    break;
                }
            }
        }

        if (frozen) {
            const int r_row = i - 1;
            const float  u  = __fmaf_rn(beff, S, omg);
            const double ud = (double)u;
            const double c  = log2(ud);                     // < 0
            const double Ad = (double)g * (double)I / (1.0 - ud);
            const double Rinf = (double)R + Ad;

            double mx = fmax((double)I, Ad);
            if (mx < 1e-300) mx = 1e-300;
            double t_d = (160.0 + log2(mx)) / (-c);        // u^t below any fp32 effect
            long long cut_ll = r_row + (long long)t_d + 8;
            long long cut4   = ((cut_ll + 3) / 4) * 4;      // multiple of 4
            if (cut4 < (long long)i) cut4 = i;
            int cut = (cut4 > (long long)steps) ? steps : (int)cut4;

            s_nrows = i; s_r = r_row; s_rsplit = i; s_cut = cut;
            s_S = S; s_Irec = I; s_A = (float)Ad; s_Rinf = (float)Rinf; s_c = c;
            g_S = S; g_Rinf = (float)Rinf; g_cut = cut;
        } else {
            // Fallback: finish serially straight to gmem; tail kernel no-ops.
            s_nrows = i; s_r = steps - 1; s_rsplit = steps; s_cut = steps;
            for (; i < steps; ++i) {
                float u  = __fmaf_rn(beff, S, omg);
                float v  = __fmul_rn(beff, I);
                float nI = __fmul_rn(I, u);
                float nS = __fmaf_rn(-v, S, S);
                float nR = __fmaf_rn(g, I, R);
                S = nS; I = nI; R = nR;
                out[3*i] = S; out[3*i+1] = I; out[3*i+2] = R;
            }
            s_S = S; s_Irec = I; s_A = 0.0f; s_Rinf = R; s_c = 0.0;
            g_S = S; g_Rinf = R; g_cut = steps;
        }
    }

    __syncthreads();

    // (a) Head copy smem -> gmem, coalesced float4 (s_nrows % 4 == 0 when frozen).
    {
        const int nelem  = 3 * s_nrows;
        const int count4 = nelem / 4;
        const float4* src = reinterpret_cast<const float4*>(s_rows);
        float4*       dst = reinterpret_cast<float4*>(out);
        for (int idx = tid; idx < count4; idx += 256)
            dst[idx] = src[idx];
        for (int e = count4 * 4 + tid; e < nelem; e += 256)   // tiny-steps remainder
            out[e] = s_rows[e];
    }

    // (b) Transition rows [rsplit, cut): closed form, element-parallel.
    {
        const int   r    = s_r;
        const float S    = s_S;
        const float Irec = s_Irec;
        const float A    = s_A;
        const float Rinf = s_Rinf;
        const double c   = s_c;
        const int eBeg = 3 * s_rsplit;
        const int eEnd = 3 * s_cut;
        for (int e = eBeg + tid; e < eEnd; e += 256) {
            const int k    = e / 3;
            const int comp = e - 3 * k;
            const float p  = exp2f((float)((double)(k - r) * c));
            out[e] = (comp == 0) ? S
                   : (comp == 1) ? __fmul_rn(Irec, p)
                                 : __fmaf_rn(-A, p, Rinf);
        }
    }
}

// ---------------------------------------------------------------------------
// Kernel B: constant region [g_cut, steps) = (S, 0, Rinf).
// Block tile = blockDim*4 float4s; each thread stores 4 float4s at stride
// blockDim (every STG.128 wavefront fully coalesced). One %3 per thread;
// phase rotates +1 per store since blockDim=256 == 1 (mod 3).
// 3*g_cut is a multiple of 12 -> start4 is a float4 index with phase start4%3.
// ---------------------------------------------------------------------------
__global__ void __launch_bounds__(256)
sir_fill_kernel(float* __restrict__ out, int total_elems)
{
    const int n4     = total_elems / 4;
    const int start4 = (3 * g_cut) / 4;          // multiple of 3

    const float v0 = g_S, v1 = 0.0f, v2 = g_Rinf;
    const float4 P0 = make_float4(v0, v1, v2, v0);
    const float4 P1 = make_float4(v1, v2, v0, v1);
    const float4 P2 = make_float4(v2, v0, v1, v2);

    float4* out4 = reinterpret_cast<float4*>(out);

    const int j0 = start4 + blockIdx.x * (256 * 4) + threadIdx.x;
    int ph = j0 % 3;
    #pragma unroll
    for (int it = 0; it < 4; ++it) {
        const int j = j0 + it * 256;
        if (j < n4) {
            out4[j] = (ph == 0) ? P0 : ((ph == 1) ? P1 : P2);
        }
        ph = (ph == 2) ? 0 : ph + 1;
    }

    // Scalar remainder (total_elems % 4 != 0 — not hit for steps = 4M).
    if (blockIdx.x == 0 && threadIdx.x == 0) {
        for (int e = n4 * 4; e < total_elems; ++e) {
            if (e >= 3 * g_cut) {
                const int m = e % 3;
                out[e] = (m == 0) ? v0 : ((m == 1) ? v1 : v2);
            }
        }
    }
}

extern "C" void kernel_launch(void* const* d_in, const int* in_sizes, int n_in,
                              void* d_out, int out_size)
{
    const float* x  = (const float*)d_in[0];
    const float* bw = (const float*)d_in[1];
    const float* gw = (const float*)d_in[2];
    float* out = (float*)d_out;

    const int steps = out_size / 3;

    sir_scan_kernel<<<1, 256>>>(x, bw, gw, steps, out);

    // Grid sized for worst case (cut == 0): each block covers 1024 float4s.
    const int n4 = out_size / 4;
    int blocks = (n4 + 1024 - 1) / 1024;
    if (blocks < 1) blocks = 1;
    sir_fill_kernel<<<blocks, 256>>>(out, out_size);
}

// round 6
// speedup vs baseline: 1.6277x; 1.6277x over previous
#include <cuda_runtime.h>
#include <math.h>

#define SMEM_ROWS 2048     // 24 KB row buffer; freeze expected at ~293 rows
#define NTHREADS  256
#define NBLOCKS   592      // 4 blocks/SM * 148 SMs -> single wave

// ---------------------------------------------------------------------------
// Single fused kernel. EVERY block redundantly runs the short serial prologue
// (deterministic, ~293 iters) into its own SMEM, so all blocks independently
// know: the head trajectory, the frozen state, and the closed-form params.
// No cross-block communication, no device globals, one launch.
//
// Recurrence (algebraically identical to reference, single rounding each):
//   u = 1-g+beff*S ; nI = I*u ; nS = fma(-beff*I,S,S) ; nR = fma(g,I,R)
// After S bitwise-freezes (monotone non-increasing => permanent once an
// 8-iter chunk leaves it unchanged, with 0<u<1), the tail is exactly
// geometric: I_m = Irec*u^m, R_m = Rinf - A*u^m, S frozen; past `cut`
// (u^m below every fp32 effect) rows are the constant (S, 0, Rinf).
// ---------------------------------------------------------------------------
__global__ void __launch_bounds__(NTHREADS)
sir_fused_kernel(const float* __restrict__ x,
                 const float* __restrict__ bw,
                 const float* __restrict__ gw,
                 int steps, int total_elems,
                 float* __restrict__ out)
{
    __shared__ __align__(16) float s_rows[SMEM_ROWS * 3];
    __shared__ int    s_nrows, s_r, s_cut;      // rsplit == s_nrows
    __shared__ float  s_S, s_Irec, s_A, s_Rinf;
    __shared__ double s_c;

    const int tid = threadIdx.x;

    // ---------------- Prologue: serial scan (thread 0 of every block) -----
    if (tid == 0) {
        float S = x[0], I = x[1], R = x[2];
        const float pop  = __fadd_rn(__fadd_rn(x[0], x[1]), x[2]);
        const float g    = gw[0];
        const float beff = (pop == 1.0f) ? bw[0] : __fdiv_rn(bw[0], pop);
        const float omg  = __fsub_rn(1.0f, g);

        s_rows[0] = S; s_rows[1] = I; s_rows[2] = R;

        int i = 1;
        // Head rows 1..3 so the chunk loop starts at i=4 (keeps i % 4 == 0 at exit).
        for (int h = 0; h < 3 && i < steps; ++h, ++i) {
            float u  = __fmaf_rn(beff, S, omg);
            float v  = __fmul_rn(beff, I);
            float nI = __fmul_rn(I, u);
            float nS = __fmaf_rn(-v, S, S);
            float nR = __fmaf_rn(g, I, R);
            S = nS; I = nI; R = nR;
            s_rows[3*i] = S; s_rows[3*i+1] = I; s_rows[3*i+2] = R;
        }

        bool frozen = false;
        const int cap = (steps < SMEM_ROWS) ? steps : SMEM_ROWS;
        for (; i + 8 <= cap; i += 8) {
            const float S0 = S;
            #pragma unroll
            for (int k = 0; k < 8; ++k) {
                float u  = __fmaf_rn(beff, S, omg);
                float v  = __fmul_rn(beff, I);
                float nI = __fmul_rn(I, u);
                float nS = __fmaf_rn(-v, S, S);
                float nR = __fmaf_rn(g, I, R);
                S = nS; I = nI; R = nR;
                float* row = s_rows + 3 * (i + k);
                row[0] = S; row[1] = I; row[2] = R;
            }
            if (S == S0) {
                float u = __fmaf_rn(beff, S, omg);
                if (u < 1.0f && u > 0.0f) {    // contracting: S frozen forever
                    i += 8;                     // rows [0, i) buffered; state = row i-1
                    frozen = true;
                    break;
                }
            }
        }

        if (frozen) {
            const int r_row = i - 1;
            const float  u  = __fmaf_rn(beff, S, omg);
            const double ud = (double)u;
            const double c  = log2(ud);                    // < 0
            const double Ad = (double)g * (double)I / (1.0 - ud);
            const double Rinf = (double)R + Ad;

            double mx = fmax((double)I, Ad);
            if (mx < 1e-300) mx = 1e-300;
            double t_d = (160.0 + log2(mx)) / (-c);        // u^t below any fp32 effect
            long long cut_ll = r_row + (long long)t_d + 8;
            long long cut4   = ((cut_ll + 3) / 4) * 4;     // multiple of 4
            if (cut4 < (long long)i) cut4 = i;
            int cut = (cut4 > (long long)steps) ? steps : (int)cut4;

            s_nrows = i; s_r = r_row; s_cut = cut;
            s_S = S; s_Irec = I; s_A = (float)Ad; s_Rinf = (float)Rinf; s_c = c;
        } else {
            // Fallback (non-contracting / tiny steps): finish serially to gmem.
            // All blocks write identical values to identical addresses: benign.
            s_nrows = i; s_r = steps - 1; s_cut = steps;
            for (; i < steps; ++i) {
                float u  = __fmaf_rn(beff, S, omg);
                float v  = __fmul_rn(beff, I);
                float nI = __fmul_rn(I, u);
                float nS = __fmaf_rn(-v, S, S);
                float nR = __fmaf_rn(g, I, R);
                S = nS; I = nI; R = nR;
                out[3*i] = S; out[3*i+1] = I; out[3*i+2] = R;
            }
            s_S = S; s_Irec = I; s_A = 0.0f; s_Rinf = R; s_c = 0.0;
        }
    }

    __syncthreads();

    const int gsize = gridDim.x * NTHREADS;
    const int gtid  = blockIdx.x * NTHREADS + tid;

    const int   nrows = s_nrows;       // == rsplit; multiple of 4 when frozen
    const int   r     = s_r;
    const int   cut   = s_cut;
    const float S     = s_S;
    const float Irec  = s_Irec;
    const float A     = s_A;
    const float Rinf  = s_Rinf;
    const double c    = s_c;

    // ---- (a) Head rows [0, nrows): every block holds them in local SMEM ----
    {
        const int nelem  = 3 * nrows;
        const int count4 = nelem / 4;
        const float4* src = reinterpret_cast<const float4*>(s_rows);
        float4*       dst = reinterpret_cast<float4*>(out);
        for (int idx = gtid; idx < count4; idx += gsize)
            dst[idx] = src[idx];
        for (int e = count4 * 4 + gtid; e < nelem; e += gsize)   // tiny-steps remainder
            out[e] = s_rows[e];
    }

    // ---- (b) Transition rows [nrows, cut): geometric closed form ----------
    {
        const int eBeg = 3 * nrows;
        const int eEnd = 3 * cut;
        for (int e = eBeg + gtid; e < eEnd; e += gsize) {
            const int k    = e / 3;
            const int comp = e - 3 * k;
            const float p  = exp2f((float)((double)(k - r) * c));
            out[e] = (comp == 0) ? S
                   : (comp == 1) ? __fmul_rn(Irec, p)
                                 : __fmaf_rn(-A, p, Rinf);
        }
    }

    // ---- (c) Constant region [cut, steps): (S, 0, Rinf) -------------------
    // R3-proven fastest shape: one float4 per thread-iteration, grid-stride.
    // 3*cut % 12 == 0 -> start4 is a valid float4 index; phase = j % 3.
    {
        const int n4     = total_elems / 4;
        const int start4 = (3 * cut) / 4;

        const float4 P0 = make_float4(S,    0.0f, Rinf, S);
        const float4 P1 = make_float4(0.0f, Rinf, S,    0.0f);
        const float4 P2 = make_float4(Rinf, S,    0.0f, Rinf);

        float4* out4 = reinterpret_cast<float4*>(out);
        for (int j = start4 + gtid; j < n4; j += gsize) {
            const int ph = j % 3;
            out4[j] = (ph == 0) ? P0 : ((ph == 1) ? P1 : P2);
        }

        // Scalar remainder (total_elems % 4 != 0 — not hit for steps = 4M).
        if (gtid == 0) {
            for (int e = n4 * 4; e < total_elems; ++e) {
                const int k    = e / 3;
                const int comp = e - 3 * k;
                if (k >= cut) {
                    out[e] = (comp == 0) ? S : ((comp == 1) ? 0.0f : Rinf);
                } else if (k >= nrows) {
                    const float p = exp2f((float)((double)(k - r) * c));
                    out[e] = (comp == 0) ? S
                           : (comp == 1) ? __fmul_rn(Irec, p)
                                         : __fmaf_rn(-A, p, Rinf);
                } else {
                    out[e] = s_rows[e];
                }
            }
        }
    }
}

extern "C" void kernel_launch(void* const* d_in, const int* in_sizes, int n_in,
                              void* d_out, int out_size)
{
    const float* x  = (const float*)d_in[0];
    const float* bw = (const float*)d_in[1];
    const float* gw = (const float*)d_in[2];
    float* out = (float*)d_out;

    const int steps = out_size / 3;

    sir_fused_kernel<<<NBLOCKS, NTHREADS>>>(x, bw, gw, steps, out_size, out);
}